// round 1
// baseline (speedup 1.0000x reference)
#include <cuda_runtime.h>
#include <math.h>

#define DEVINL __device__ __forceinline__

typedef unsigned long long u64;

// ---------------- packed f32x2 helpers (sm_100+ PTX) ----------------
DEVINL u64 pack2(float lo, float hi) {
    u64 r;
    asm("mov.b64 %0, {%1, %2};" : "=l"(r) : "f"(lo), "f"(hi));
    return r;
}
DEVINL void unpack2(u64 v, float &lo, float &hi) {
    asm("mov.b64 {%0, %1}, %2;" : "=f"(lo), "=f"(hi) : "l"(v));
}
DEVINL void fma2(u64 &d, u64 a, u64 b) {
    asm("fma.rn.f32x2 %0, %1, %2, %0;" : "+l"(d) : "l"(a), "l"(b));
}
DEVINL void mul2(u64 &d, u64 a) {
    asm("mul.rn.f32x2 %0, %0, %1;" : "+l"(d) : "l"(a));
}

DEVINL float gelu_exact(float x) {
    return 0.5f * x * (1.0f + erff(x * 0.7071067811865475f));
}

// ---------------- problem constants ----------------
// B=2, S=4096, D=768, H=12, dk=64, FFN hidden=3072, M = B*S = 8192
static const int M_TOK = 8192;
static const int D_MODEL = 768;
static const int D_FFN = 3072;

// ---------------- scratch (device globals; no allocations allowed) ----------------
__device__ float g_q[8192 * 768];
__device__ float g_k[8192 * 768];
__device__ float g_v[8192 * 768];
__device__ float g_ctx[8192 * 768];
__device__ float g_y1[8192 * 768];
__device__ float g_n1[8192 * 768];
__device__ float g_h[8192 * 3072];
__device__ float g_y2[8192 * 768];

// =====================================================================
// NT SGEMM: C[M,N] = A[M,K] @ B[N,K]^T (+ bias, + epilogue)
// EPI: 0 = +bias, 1 = +bias then exact GELU, 2 = +bias +residual
// BM=BN=128, BK=16, 256 threads, 8x8 per thread, f32x2 accumulators,
// register prefetch pipelining. Requires M%128==0, N%128==0, K%16==0.
// =====================================================================
template <int EPI>
__global__ void __launch_bounds__(256) gemm_nt(
    const float* __restrict__ A,
    const float* __restrict__ B,
    const float* __restrict__ bias,
    const float* __restrict__ res,
    float* __restrict__ C,
    int M, int N, int K)
{
    __shared__ float As[16][128];
    __shared__ float Bs[16][128];

    const int tid = threadIdx.x;
    const int bm = blockIdx.y * 128;
    const int bn = blockIdx.x * 128;

    // load mapping: each thread loads a float4 from 2 rows (r, r+64) of A and B
    const int lr = tid >> 2;           // 0..63
    const int lc = (tid & 3) << 2;     // 0,4,8,12
    const float* Ag = A + (long)(bm + lr) * K + lc;
    const float* Bg = B + (long)(bn + lr) * K + lc;

    // compute mapping: quadrant layout (rows ty*4 / 64+ty*4, cols tx*4 / 64+tx*4)
    const int ty = tid >> 4;           // 0..15
    const int tx = tid & 15;           // 0..15

    u64 acc[8][4];
#pragma unroll
    for (int i = 0; i < 8; i++)
#pragma unroll
        for (int j = 0; j < 4; j++) acc[i][j] = 0ull;

    float4 pa0, pa1, pb0, pb1;

    // prologue: load tile 0
    pa0 = *(const float4*)(Ag);
    pa1 = *(const float4*)(Ag + (long)64 * K);
    pb0 = *(const float4*)(Bg);
    pb1 = *(const float4*)(Bg + (long)64 * K);
    As[lc + 0][lr] = pa0.x; As[lc + 1][lr] = pa0.y; As[lc + 2][lr] = pa0.z; As[lc + 3][lr] = pa0.w;
    As[lc + 0][lr + 64] = pa1.x; As[lc + 1][lr + 64] = pa1.y; As[lc + 2][lr + 64] = pa1.z; As[lc + 3][lr + 64] = pa1.w;
    Bs[lc + 0][lr] = pb0.x; Bs[lc + 1][lr] = pb0.y; Bs[lc + 2][lr] = pb0.z; Bs[lc + 3][lr] = pb0.w;
    Bs[lc + 0][lr + 64] = pb1.x; Bs[lc + 1][lr + 64] = pb1.y; Bs[lc + 2][lr + 64] = pb1.z; Bs[lc + 3][lr + 64] = pb1.w;
    __syncthreads();

    const int nk = K >> 4;
    for (int t = 1; t <= nk; ++t) {
        if (t < nk) {
            const float* Ap = Ag + t * 16;
            const float* Bp = Bg + t * 16;
            pa0 = *(const float4*)(Ap);
            pa1 = *(const float4*)(Ap + (long)64 * K);
            pb0 = *(const float4*)(Bp);
            pb1 = *(const float4*)(Bp + (long)64 * K);
        }
#pragma unroll
        for (int kk = 0; kk < 16; kk++) {
            float4 a0 = *(const float4*)(&As[kk][ty * 4]);
            float4 a1 = *(const float4*)(&As[kk][64 + ty * 4]);
            ulonglong2 b0 = *(const ulonglong2*)(&Bs[kk][tx * 4]);
            ulonglong2 b1 = *(const ulonglong2*)(&Bs[kk][64 + tx * 4]);
            float ar[8] = {a0.x, a0.y, a0.z, a0.w, a1.x, a1.y, a1.z, a1.w};
#pragma unroll
            for (int i = 0; i < 8; i++) {
                u64 ap = pack2(ar[i], ar[i]);
                fma2(acc[i][0], ap, b0.x);
                fma2(acc[i][1], ap, b0.y);
                fma2(acc[i][2], ap, b1.x);
                fma2(acc[i][3], ap, b1.y);
            }
        }
        __syncthreads();
        if (t < nk) {
            As[lc + 0][lr] = pa0.x; As[lc + 1][lr] = pa0.y; As[lc + 2][lr] = pa0.z; As[lc + 3][lr] = pa0.w;
            As[lc + 0][lr + 64] = pa1.x; As[lc + 1][lr + 64] = pa1.y; As[lc + 2][lr + 64] = pa1.z; As[lc + 3][lr + 64] = pa1.w;
            Bs[lc + 0][lr] = pb0.x; Bs[lc + 1][lr] = pb0.y; Bs[lc + 2][lr] = pb0.z; Bs[lc + 3][lr] = pb0.w;
            Bs[lc + 0][lr + 64] = pb1.x; Bs[lc + 1][lr + 64] = pb1.y; Bs[lc + 2][lr + 64] = pb1.z; Bs[lc + 3][lr + 64] = pb1.w;
            __syncthreads();
        }
    }

    // epilogue
#pragma unroll
    for (int i = 0; i < 8; i++) {
        int lm = (i < 4) ? (ty * 4 + i) : (64 + ty * 4 + (i - 4));
        long gm = bm + lm;
#pragma unroll
        for (int q2 = 0; q2 < 2; q2++) {
            int gn = bn + q2 * 64 + tx * 4;
            float x0, x1, x2, x3;
            unpack2(acc[i][q2 * 2 + 0], x0, x1);
            unpack2(acc[i][q2 * 2 + 1], x2, x3);
            float4 bv = *(const float4*)(bias + gn);
            x0 += bv.x; x1 += bv.y; x2 += bv.z; x3 += bv.w;
            if (EPI == 1) {
                x0 = gelu_exact(x0); x1 = gelu_exact(x1);
                x2 = gelu_exact(x2); x3 = gelu_exact(x3);
            }
            if (EPI == 2) {
                float4 rv = *(const float4*)(res + gm * N + gn);
                x0 += rv.x; x1 += rv.y; x2 += rv.z; x3 += rv.w;
            }
            float4 ov = make_float4(x0, x1, x2, x3);
            *(float4*)(C + gm * N + gn) = ov;
        }
    }
}

// =====================================================================
// fp32 flash attention, d_k=64, BM=BN=64, 256 threads (16x16 layout),
// 4x4 fragment per thread, online softmax, P written back into K's smem
// buffer. Q pre-scaled by 1/sqrt(64). Dynamic smem = 50176 B.
// Grid: (S/64, B*H). Q/K/V/O are [B*S, 768] with head slice at h*64.
// =====================================================================
#define FLASH_SMEM 50176

__global__ void __launch_bounds__(256) flash_attn(
    const float* __restrict__ Q,
    const float* __restrict__ Kg,
    const float* __restrict__ Vg,
    float* __restrict__ O)
{
    extern __shared__ float sm[];
    float* Qs = sm;                 // [64][64]
    float* KP = sm + 64 * 64;       // [64][68]  K tile, then reused for P
    float* Vs = KP + 64 * 68;       // [64][64]

    const int tid = threadIdx.x;
    const int ty = tid >> 4;        // 0..15
    const int tx = tid & 15;        // 0..15
    const int bh = blockIdx.y;
    const int b = bh / 12;
    const int h = bh - b * 12;
    const int q0 = blockIdx.x * 64;
    const long rowbase = (long)b * 4096;

    // ---- load Q tile, scaled by 1/8 ----
    {
        const float* Qbase = Q + (rowbase + q0) * 768 + h * 64;
        int r = tid >> 4;
        int c = (tid & 15) * 4;
#pragma unroll
        for (int p = 0; p < 4; p++) {
            float4 v = *(const float4*)(Qbase + (long)(p * 16 + r) * 768 + c);
            v.x *= 0.125f; v.y *= 0.125f; v.z *= 0.125f; v.w *= 0.125f;
            *(float4*)(Qs + (p * 16 + r) * 64 + c) = v;
        }
    }

    u64 o[4][2];
    float m_i[4], l_i[4];
#pragma unroll
    for (int i = 0; i < 4; i++) { o[i][0] = 0ull; o[i][1] = 0ull; m_i[i] = -1e30f; l_i[i] = 0.0f; }

    for (int kt = 0; kt < 64; ++kt) {
        __syncthreads();   // protect KP/Vs from previous iteration's readers; also fences Qs on iter 0
        {
            const float* Kb = Kg + (rowbase + kt * 64) * 768 + h * 64;
            const float* Vb = Vg + (rowbase + kt * 64) * 768 + h * 64;
            int r = tid >> 4;
            int c = (tid & 15) * 4;
#pragma unroll
            for (int p = 0; p < 4; p++) {
                *(float4*)(KP + (p * 16 + r) * 68 + c) = *(const float4*)(Kb + (long)(p * 16 + r) * 768 + c);
                *(float4*)(Vs + (p * 16 + r) * 64 + c) = *(const float4*)(Vb + (long)(p * 16 + r) * 768 + c);
            }
        }
        __syncthreads();

        // ---- S = Q K^T (f32x2 pairwise accumulation over k) ----
        u64 s2[4][4];
#pragma unroll
        for (int i = 0; i < 4; i++)
#pragma unroll
            for (int j = 0; j < 4; j++) s2[i][j] = 0ull;

#pragma unroll
        for (int kk = 0; kk < 64; kk += 4) {
            ulonglong2 qv[4], kv[4];
#pragma unroll
            for (int i = 0; i < 4; i++) qv[i] = *(const ulonglong2*)(Qs + (ty * 4 + i) * 64 + kk);
#pragma unroll
            for (int j = 0; j < 4; j++) kv[j] = *(const ulonglong2*)(KP + (tx * 4 + j) * 68 + kk);
#pragma unroll
            for (int i = 0; i < 4; i++)
#pragma unroll
                for (int j = 0; j < 4; j++) {
                    fma2(s2[i][j], qv[i].x, kv[j].x);
                    fma2(s2[i][j], qv[i].y, kv[j].y);
                }
        }
        __syncthreads();   // all S-gemm reads of KP complete before P overwrites it

        // ---- online softmax; write P into KP buffer ----
#pragma unroll
        for (int i = 0; i < 4; i++) {
            float lo, hi;
            float s0, s1, sv2, s3;
            unpack2(s2[i][0], lo, hi); s0 = lo + hi;
            unpack2(s2[i][1], lo, hi); s1 = lo + hi;
            unpack2(s2[i][2], lo, hi); sv2 = lo + hi;
            unpack2(s2[i][3], lo, hi); s3 = lo + hi;
            float mx = fmaxf(fmaxf(s0, s1), fmaxf(sv2, s3));
#pragma unroll
            for (int d = 8; d; d >>= 1) mx = fmaxf(mx, __shfl_xor_sync(0xffffffffu, mx, d));
            float mn = fmaxf(m_i[i], mx);
            float alpha = __expf(m_i[i] - mn);
            m_i[i] = mn;
            float p0 = __expf(s0 - mn);
            float p1 = __expf(s1 - mn);
            float p2 = __expf(sv2 - mn);
            float p3 = __expf(s3 - mn);
            float rs = p0 + p1 + p2 + p3;
#pragma unroll
            for (int d = 8; d; d >>= 1) rs += __shfl_xor_sync(0xffffffffu, rs, d);
            l_i[i] = l_i[i] * alpha + rs;
            u64 ap = pack2(alpha, alpha);
            mul2(o[i][0], ap);
            mul2(o[i][1], ap);
            *(float4*)(KP + (ty * 4 + i) * 68 + tx * 4) = make_float4(p0, p1, p2, p3);
        }
        __syncthreads();

        // ---- O += P V ----
#pragma unroll 8
        for (int kk = 0; kk < 64; kk++) {
            ulonglong2 vv = *(const ulonglong2*)(Vs + kk * 64 + tx * 4);
#pragma unroll
            for (int i = 0; i < 4; i++) {
                float pv = KP[(ty * 4 + i) * 68 + kk];
                u64 pp = pack2(pv, pv);
                fma2(o[i][0], pp, vv.x);
                fma2(o[i][1], pp, vv.y);
            }
        }
    }

    // ---- normalize and write out ----
    float* Ob = O + (rowbase + q0) * 768 + h * 64;
#pragma unroll
    for (int i = 0; i < 4; i++) {
        float inv = 1.0f / l_i[i];
        float c0, c1, c2, c3;
        unpack2(o[i][0], c0, c1);
        unpack2(o[i][1], c2, c3);
        float4 ov = make_float4(c0 * inv, c1 * inv, c2 * inv, c3 * inv);
        *(float4*)(Ob + (long)(ty * 4 + i) * 768 + tx * 4) = ov;
    }
}

// =====================================================================
// LayerNorm over last dim (768). One block (256 thr) per row.
// =====================================================================
__global__ void __launch_bounds__(256) layernorm_k(
    const float* __restrict__ X,
    const float* __restrict__ g,
    const float* __restrict__ bta,
    float* __restrict__ Y)
{
    const long row = blockIdx.x;
    const float* x = X + row * 768;
    const int tid = threadIdx.x;
    float v0 = x[tid], v1 = x[tid + 256], v2 = x[tid + 512];
    float s = v0 + v1 + v2;
    float ss = v0 * v0 + v1 * v1 + v2 * v2;
#pragma unroll
    for (int d = 16; d; d >>= 1) {
        s += __shfl_xor_sync(0xffffffffu, s, d);
        ss += __shfl_xor_sync(0xffffffffu, ss, d);
    }
    __shared__ float r0[8], r1[8];
    if ((tid & 31) == 0) { r0[tid >> 5] = s; r1[tid >> 5] = ss; }
    __syncthreads();
    float tot = 0.0f, tot2 = 0.0f;
#pragma unroll
    for (int w = 0; w < 8; w++) { tot += r0[w]; tot2 += r1[w]; }
    const float invD = 1.0f / 768.0f;
    float mu = tot * invD;
    float var = tot2 * invD - mu * mu;
    float rstd = rsqrtf(var + 1e-5f);
    float* y = Y + row * 768;
    y[tid]       = (v0 - mu) * rstd * g[tid]       + bta[tid];
    y[tid + 256] = (v1 - mu) * rstd * g[tid + 256] + bta[tid + 256];
    y[tid + 512] = (v2 - mu) * rstd * g[tid + 512] + bta[tid + 512];
}

// =====================================================================
// host launcher (graph-capturable: kernel launches only)
// =====================================================================
extern "C" void kernel_launch(void* const* d_in, const int* in_sizes, int n_in,
                              void* d_out, int out_size)
{
    (void)in_sizes; (void)n_in; (void)out_size;
    const float* x   = (const float*)d_in[0];
    const float* wq  = (const float*)d_in[1];
    const float* bq  = (const float*)d_in[2];
    const float* wk  = (const float*)d_in[3];
    const float* bk  = (const float*)d_in[4];
    const float* wv  = (const float*)d_in[5];
    const float* bv  = (const float*)d_in[6];
    const float* wo  = (const float*)d_in[7];
    const float* bo  = (const float*)d_in[8];
    const float* w1  = (const float*)d_in[9];
    const float* b1  = (const float*)d_in[10];
    const float* w2  = (const float*)d_in[11];
    const float* b2  = (const float*)d_in[12];
    const float* g1  = (const float*)d_in[13];
    const float* be1 = (const float*)d_in[14];
    const float* g2  = (const float*)d_in[15];
    const float* be2 = (const float*)d_in[16];
    float* out = (float*)d_out;

    float *q, *k, *v, *ctx, *y1, *n1, *hbuf, *y2;
    cudaGetSymbolAddress((void**)&q,    g_q);
    cudaGetSymbolAddress((void**)&k,    g_k);
    cudaGetSymbolAddress((void**)&v,    g_v);
    cudaGetSymbolAddress((void**)&ctx,  g_ctx);
    cudaGetSymbolAddress((void**)&y1,   g_y1);
    cudaGetSymbolAddress((void**)&n1,   g_n1);
    cudaGetSymbolAddress((void**)&hbuf, g_h);
    cudaGetSymbolAddress((void**)&y2,   g_y2);

    cudaFuncSetAttribute(flash_attn, cudaFuncAttributeMaxDynamicSharedMemorySize, FLASH_SMEM);

    dim3 blk(256);
    dim3 gp768(768 / 128, M_TOK / 128);    // (6, 64)
    dim3 gp3072(3072 / 128, M_TOK / 128);  // (24, 64)

    // QKV projections
    gemm_nt<0><<<gp768, blk>>>(x, wq, bq, nullptr, q, M_TOK, D_MODEL, D_MODEL);
    gemm_nt<0><<<gp768, blk>>>(x, wk, bk, nullptr, k, M_TOK, D_MODEL, D_MODEL);
    gemm_nt<0><<<gp768, blk>>>(x, wv, bv, nullptr, v, M_TOK, D_MODEL, D_MODEL);
    // attention
    flash_attn<<<dim3(64, 24), blk, FLASH_SMEM>>>(q, k, v, ctx);
    // output projection + residual(x)
    gemm_nt<2><<<gp768, blk>>>(ctx, wo, bo, x, y1, M_TOK, D_MODEL, D_MODEL);
    layernorm_k<<<M_TOK, blk>>>(y1, g1, be1, n1);
    // FFN
    gemm_nt<1><<<gp3072, blk>>>(n1, w1, b1, nullptr, hbuf, M_TOK, D_FFN, D_MODEL);
    gemm_nt<2><<<gp768, blk>>>(hbuf, w2, b2, n1, y2, M_TOK, D_MODEL, D_FFN);
    layernorm_k<<<M_TOK, blk>>>(y2, g2, be2, out);
}

// round 2
// speedup vs baseline: 1.4292x; 1.4292x over previous
#include <cuda_runtime.h>
#include <math.h>

#define DEVINL __device__ __forceinline__

typedef unsigned long long u64;

// ---------------- packed f32x2 helpers (sm_100+ PTX) ----------------
DEVINL u64 pack2(float lo, float hi) {
    u64 r;
    asm("mov.b64 %0, {%1, %2};" : "=l"(r) : "f"(lo), "f"(hi));
    return r;
}
DEVINL void unpack2(u64 v, float &lo, float &hi) {
    asm("mov.b64 {%0, %1}, %2;" : "=f"(lo), "=f"(hi) : "l"(v));
}
DEVINL void fma2(u64 &d, u64 a, u64 b) {
    asm("fma.rn.f32x2 %0, %1, %2, %0;" : "+l"(d) : "l"(a), "l"(b));
}
DEVINL void mul2(u64 &d, u64 a) {
    asm("mul.rn.f32x2 %0, %0, %1;" : "+l"(d) : "l"(a));
}

DEVINL float gelu_exact(float x) {
    return 0.5f * x * (1.0f + erff(x * 0.7071067811865475f));
}

// ---------------- problem constants ----------------
static const int M_TOK = 8192;
static const int D_MODEL = 768;
static const int D_FFN = 3072;

// ---------------- scratch (device globals; no allocations allowed) ----------------
__device__ float g_q[8192 * 768];
__device__ float g_k[8192 * 768];
__device__ float g_v[8192 * 768];
__device__ float g_ctx[8192 * 768];
__device__ float g_y1[8192 * 768];
__device__ float g_n1[8192 * 768];
__device__ float g_h[8192 * 3072];
__device__ float g_y2[8192 * 768];

// =====================================================================
// NT SGEMM: C[M,N] = A[M,K] @ B[N,K]^T (+ bias, + epilogue)  (unchanged)
// =====================================================================
template <int EPI>
__global__ void __launch_bounds__(256) gemm_nt(
    const float* __restrict__ A,
    const float* __restrict__ B,
    const float* __restrict__ bias,
    const float* __restrict__ res,
    float* __restrict__ C,
    int M, int N, int K)
{
    __shared__ float As[16][128];
    __shared__ float Bs[16][128];

    const int tid = threadIdx.x;
    const int bm = blockIdx.y * 128;
    const int bn = blockIdx.x * 128;

    const int lr = tid >> 2;
    const int lc = (tid & 3) << 2;
    const float* Ag = A + (long)(bm + lr) * K + lc;
    const float* Bg = B + (long)(bn + lr) * K + lc;

    const int ty = tid >> 4;
    const int tx = tid & 15;

    u64 acc[8][4];
#pragma unroll
    for (int i = 0; i < 8; i++)
#pragma unroll
        for (int j = 0; j < 4; j++) acc[i][j] = 0ull;

    float4 pa0, pa1, pb0, pb1;

    pa0 = *(const float4*)(Ag);
    pa1 = *(const float4*)(Ag + (long)64 * K);
    pb0 = *(const float4*)(Bg);
    pb1 = *(const float4*)(Bg + (long)64 * K);
    As[lc + 0][lr] = pa0.x; As[lc + 1][lr] = pa0.y; As[lc + 2][lr] = pa0.z; As[lc + 3][lr] = pa0.w;
    As[lc + 0][lr + 64] = pa1.x; As[lc + 1][lr + 64] = pa1.y; As[lc + 2][lr + 64] = pa1.z; As[lc + 3][lr + 64] = pa1.w;
    Bs[lc + 0][lr] = pb0.x; Bs[lc + 1][lr] = pb0.y; Bs[lc + 2][lr] = pb0.z; Bs[lc + 3][lr] = pb0.w;
    Bs[lc + 0][lr + 64] = pb1.x; Bs[lc + 1][lr + 64] = pb1.y; Bs[lc + 2][lr + 64] = pb1.z; Bs[lc + 3][lr + 64] = pb1.w;
    __syncthreads();

    const int nk = K >> 4;
    for (int t = 1; t <= nk; ++t) {
        if (t < nk) {
            const float* Ap = Ag + t * 16;
            const float* Bp = Bg + t * 16;
            pa0 = *(const float4*)(Ap);
            pa1 = *(const float4*)(Ap + (long)64 * K);
            pb0 = *(const float4*)(Bp);
            pb1 = *(const float4*)(Bp + (long)64 * K);
        }
#pragma unroll
        for (int kk = 0; kk < 16; kk++) {
            float4 a0 = *(const float4*)(&As[kk][ty * 4]);
            float4 a1 = *(const float4*)(&As[kk][64 + ty * 4]);
            ulonglong2 b0 = *(const ulonglong2*)(&Bs[kk][tx * 4]);
            ulonglong2 b1 = *(const ulonglong2*)(&Bs[kk][64 + tx * 4]);
            float ar[8] = {a0.x, a0.y, a0.z, a0.w, a1.x, a1.y, a1.z, a1.w};
#pragma unroll
            for (int i = 0; i < 8; i++) {
                u64 ap = pack2(ar[i], ar[i]);
                fma2(acc[i][0], ap, b0.x);
                fma2(acc[i][1], ap, b0.y);
                fma2(acc[i][2], ap, b1.x);
                fma2(acc[i][3], ap, b1.y);
            }
        }
        __syncthreads();
        if (t < nk) {
            As[lc + 0][lr] = pa0.x; As[lc + 1][lr] = pa0.y; As[lc + 2][lr] = pa0.z; As[lc + 3][lr] = pa0.w;
            As[lc + 0][lr + 64] = pa1.x; As[lc + 1][lr + 64] = pa1.y; As[lc + 2][lr + 64] = pa1.z; As[lc + 3][lr + 64] = pa1.w;
            Bs[lc + 0][lr] = pb0.x; Bs[lc + 1][lr] = pb0.y; Bs[lc + 2][lr] = pb0.z; Bs[lc + 3][lr] = pb0.w;
            Bs[lc + 0][lr + 64] = pb1.x; Bs[lc + 1][lr + 64] = pb1.y; Bs[lc + 2][lr + 64] = pb1.z; Bs[lc + 3][lr + 64] = pb1.w;
            __syncthreads();
        }
    }

#pragma unroll
    for (int i = 0; i < 8; i++) {
        int lm = (i < 4) ? (ty * 4 + i) : (64 + ty * 4 + (i - 4));
        long gm = bm + lm;
#pragma unroll
        for (int q2 = 0; q2 < 2; q2++) {
            int gn = bn + q2 * 64 + tx * 4;
            float x0, x1, x2, x3;
            unpack2(acc[i][q2 * 2 + 0], x0, x1);
            unpack2(acc[i][q2 * 2 + 1], x2, x3);
            float4 bv = *(const float4*)(bias + gn);
            x0 += bv.x; x1 += bv.y; x2 += bv.z; x3 += bv.w;
            if (EPI == 1) {
                x0 = gelu_exact(x0); x1 = gelu_exact(x1);
                x2 = gelu_exact(x2); x3 = gelu_exact(x3);
            }
            if (EPI == 2) {
                float4 rv = *(const float4*)(res + gm * N + gn);
                x0 += rv.x; x1 += rv.y; x2 += rv.z; x3 += rv.w;
            }
            float4 ov = make_float4(x0, x1, x2, x3);
            *(float4*)(C + gm * N + gn) = ov;
        }
    }
}

// =====================================================================
// fp32 flash attention v2: BM=128 q-rows, BN=128 keys, d_k=64.
// 256 threads (16x16). S fragment 8x8 (f32x2-packed over key pairs),
// O fragment 8x4 (f32x2-packed over d pairs).
// Q and K staged TRANSPOSED [64][132] so the S loop is 4x LDS.128 per
// k-step for 64 FMAs (1.0 B/FMA). P stored natural [128][128]:
// conflict-free STS.128 writes, broadcast float4 reads in PV.
// smem = (64*132*2 + 128*64 + 128*128) * 4 = 165888 B, 1 block/SM.
// Grid: (S/128, B*H) = (32, 24).
// =====================================================================
#define FL_PAD 132
#define FLASH_SMEM ((64 * FL_PAD * 2 + 128 * 64 + 128 * 128) * 4)

__global__ void __launch_bounds__(256) flash_attn(
    const float* __restrict__ Q,
    const float* __restrict__ Kg,
    const float* __restrict__ Vg,
    float* __restrict__ O)
{
    extern __shared__ float sm[];
    float* QsT = sm;                        // [64][132]  (k-major, q contiguous)
    float* KsT = QsT + 64 * FL_PAD;         // [64][132]  (k-major, key contiguous)
    float* Vs  = KsT + 64 * FL_PAD;         // [128][64]  (key-major, d contiguous)
    float* Ps  = Vs + 128 * 64;             // [128][128] (q-major, key contiguous)

    const int tid = threadIdx.x;
    const int ty = tid >> 4;                // 0..15
    const int tx = tid & 15;                // 0..15
    const int bh = blockIdx.y;
    const int b = bh / 12;
    const int h = bh - b * 12;
    const int q0 = blockIdx.x * 128;
    const long rowbase = (long)b * 4096;

    const int r = tid >> 4;                 // staging row lane 0..15
    const int c = (tid & 15) * 4;           // staging col 0,4,..,60

    // ---- stage Q transposed, pre-scaled by 1/sqrt(64) ----
    {
        const float* Qb = Q + (rowbase + q0) * 768 + h * 64;
#pragma unroll
        for (int p = 0; p < 8; p++) {
            int row = p * 16 + r;
            float4 v = *(const float4*)(Qb + (long)row * 768 + c);
            QsT[(c + 0) * FL_PAD + row] = v.x * 0.125f;
            QsT[(c + 1) * FL_PAD + row] = v.y * 0.125f;
            QsT[(c + 2) * FL_PAD + row] = v.z * 0.125f;
            QsT[(c + 3) * FL_PAD + row] = v.w * 0.125f;
        }
    }

    u64 o[8][2];
    float m_i[8], l_i[8];
#pragma unroll
    for (int i = 0; i < 8; i++) { o[i][0] = 0ull; o[i][1] = 0ull; m_i[i] = -1e30f; l_i[i] = 0.0f; }

    int qr[8];
#pragma unroll
    for (int i = 0; i < 8; i++) qr[i] = (i < 4) ? (ty * 4 + i) : (64 + ty * 4 + (i - 4));

    for (int kt = 0; kt < 32; ++kt) {
        __syncthreads();   // prev PV reads of Vs/Ps done; also fences QsT on iter 0
        // ---- stage K (transposed) and V (natural) ----
        {
            const float* Kb = Kg + (rowbase + kt * 128) * 768 + h * 64;
            const float* Vb = Vg + (rowbase + kt * 128) * 768 + h * 64;
#pragma unroll
            for (int p = 0; p < 8; p++) {
                int row = p * 16 + r;
                float4 kv = *(const float4*)(Kb + (long)row * 768 + c);
                KsT[(c + 0) * FL_PAD + row] = kv.x;
                KsT[(c + 1) * FL_PAD + row] = kv.y;
                KsT[(c + 2) * FL_PAD + row] = kv.z;
                KsT[(c + 3) * FL_PAD + row] = kv.w;
                *(float4*)(Vs + row * 64 + c) = *(const float4*)(Vb + (long)row * 768 + c);
            }
        }
        __syncthreads();

        // ---- S = Q K^T: outer product over k, 8x8 frag, packed over key pairs ----
        u64 s2[8][4];
#pragma unroll
        for (int i = 0; i < 8; i++)
#pragma unroll
            for (int j = 0; j < 4; j++) s2[i][j] = 0ull;

#pragma unroll 8
        for (int k = 0; k < 64; k++) {
            float4 a0 = *(const float4*)(QsT + k * FL_PAD + ty * 4);
            float4 a1 = *(const float4*)(QsT + k * FL_PAD + 64 + ty * 4);
            ulonglong2 b0 = *(const ulonglong2*)(KsT + k * FL_PAD + tx * 4);
            ulonglong2 b1 = *(const ulonglong2*)(KsT + k * FL_PAD + 64 + tx * 4);
            float ar[8] = {a0.x, a0.y, a0.z, a0.w, a1.x, a1.y, a1.z, a1.w};
#pragma unroll
            for (int i = 0; i < 8; i++) {
                u64 ap = pack2(ar[i], ar[i]);
                fma2(s2[i][0], ap, b0.x);
                fma2(s2[i][1], ap, b0.y);
                fma2(s2[i][2], ap, b1.x);
                fma2(s2[i][3], ap, b1.y);
            }
        }

        // ---- online softmax (row stats over 16 tx lanes); write P (natural) ----
#pragma unroll
        for (int i = 0; i < 8; i++) {
            float s0, s1, s2f, s3, s4, s5, s6, s7;
            unpack2(s2[i][0], s0, s1);
            unpack2(s2[i][1], s2f, s3);
            unpack2(s2[i][2], s4, s5);
            unpack2(s2[i][3], s6, s7);
            float mx = fmaxf(fmaxf(fmaxf(s0, s1), fmaxf(s2f, s3)),
                             fmaxf(fmaxf(s4, s5), fmaxf(s6, s7)));
#pragma unroll
            for (int d = 8; d; d >>= 1) mx = fmaxf(mx, __shfl_xor_sync(0xffffffffu, mx, d));
            float mn = fmaxf(m_i[i], mx);
            float alpha = __expf(m_i[i] - mn);
            m_i[i] = mn;
            float p0 = __expf(s0 - mn), p1 = __expf(s1 - mn);
            float p2 = __expf(s2f - mn), p3 = __expf(s3 - mn);
            float p4 = __expf(s4 - mn), p5 = __expf(s5 - mn);
            float p6 = __expf(s6 - mn), p7 = __expf(s7 - mn);
            float rs = (p0 + p1) + (p2 + p3) + (p4 + p5) + (p6 + p7);
#pragma unroll
            for (int d = 8; d; d >>= 1) rs += __shfl_xor_sync(0xffffffffu, rs, d);
            l_i[i] = l_i[i] * alpha + rs;
            u64 ap = pack2(alpha, alpha);
            mul2(o[i][0], ap);
            mul2(o[i][1], ap);
            *(float4*)(Ps + qr[i] * 128 + tx * 4)      = make_float4(p0, p1, p2, p3);
            *(float4*)(Ps + qr[i] * 128 + 64 + tx * 4) = make_float4(p4, p5, p6, p7);
        }
        __syncthreads();

        // ---- O += P V : per 4 keys, broadcast-float4 P reads + vector V reads ----
#pragma unroll 2
        for (int kk4 = 0; kk4 < 32; kk4++) {
            float4 pr[8];
#pragma unroll
            for (int i = 0; i < 8; i++)
                pr[i] = *(const float4*)(Ps + qr[i] * 128 + kk4 * 4);
            ulonglong2 vv[4];
#pragma unroll
            for (int u = 0; u < 4; u++)
                vv[u] = *(const ulonglong2*)(Vs + (kk4 * 4 + u) * 64 + tx * 4);
#pragma unroll
            for (int u = 0; u < 4; u++) {
#pragma unroll
                for (int i = 0; i < 8; i++) {
                    float pv = (u == 0) ? pr[i].x : (u == 1) ? pr[i].y : (u == 2) ? pr[i].z : pr[i].w;
                    u64 pp = pack2(pv, pv);
                    fma2(o[i][0], pp, vv[u].x);
                    fma2(o[i][1], pp, vv[u].y);
                }
            }
        }
    }

    // ---- normalize and write out ----
    float* Ob = O + (rowbase + q0) * 768 + h * 64;
#pragma unroll
    for (int i = 0; i < 8; i++) {
        float inv = 1.0f / l_i[i];
        float c0, c1, c2, c3;
        unpack2(o[i][0], c0, c1);
        unpack2(o[i][1], c2, c3);
        float4 ov = make_float4(c0 * inv, c1 * inv, c2 * inv, c3 * inv);
        *(float4*)(Ob + (long)qr[i] * 768 + tx * 4) = ov;
    }
}

// =====================================================================
// LayerNorm over last dim (768). One block (256 thr) per row. (unchanged)
// =====================================================================
__global__ void __launch_bounds__(256) layernorm_k(
    const float* __restrict__ X,
    const float* __restrict__ g,
    const float* __restrict__ bta,
    float* __restrict__ Y)
{
    const long row = blockIdx.x;
    const float* x = X + row * 768;
    const int tid = threadIdx.x;
    float v0 = x[tid], v1 = x[tid + 256], v2 = x[tid + 512];
    float s = v0 + v1 + v2;
    float ss = v0 * v0 + v1 * v1 + v2 * v2;
#pragma unroll
    for (int d = 16; d; d >>= 1) {
        s += __shfl_xor_sync(0xffffffffu, s, d);
        ss += __shfl_xor_sync(0xffffffffu, ss, d);
    }
    __shared__ float r0[8], r1[8];
    if ((tid & 31) == 0) { r0[tid >> 5] = s; r1[tid >> 5] = ss; }
    __syncthreads();
    float tot = 0.0f, tot2 = 0.0f;
#pragma unroll
    for (int w = 0; w < 8; w++) { tot += r0[w]; tot2 += r1[w]; }
    const float invD = 1.0f / 768.0f;
    float mu = tot * invD;
    float var = tot2 * invD - mu * mu;
    float rstd = rsqrtf(var + 1e-5f);
    float* y = Y + row * 768;
    y[tid]       = (v0 - mu) * rstd * g[tid]       + bta[tid];
    y[tid + 256] = (v1 - mu) * rstd * g[tid + 256] + bta[tid + 256];
    y[tid + 512] = (v2 - mu) * rstd * g[tid + 512] + bta[tid + 512];
}

// =====================================================================
// host launcher (graph-capturable: kernel launches only)
// =====================================================================
extern "C" void kernel_launch(void* const* d_in, const int* in_sizes, int n_in,
                              void* d_out, int out_size)
{
    (void)in_sizes; (void)n_in; (void)out_size;
    const float* x   = (const float*)d_in[0];
    const float* wq  = (const float*)d_in[1];
    const float* bq  = (const float*)d_in[2];
    const float* wk  = (const float*)d_in[3];
    const float* bk  = (const float*)d_in[4];
    const float* wv  = (const float*)d_in[5];
    const float* bv  = (const float*)d_in[6];
    const float* wo  = (const float*)d_in[7];
    const float* bo  = (const float*)d_in[8];
    const float* w1  = (const float*)d_in[9];
    const float* b1  = (const float*)d_in[10];
    const float* w2  = (const float*)d_in[11];
    const float* b2  = (const float*)d_in[12];
    const float* g1  = (const float*)d_in[13];
    const float* be1 = (const float*)d_in[14];
    const float* g2  = (const float*)d_in[15];
    const float* be2 = (const float*)d_in[16];
    float* out = (float*)d_out;

    float *q, *k, *v, *ctx, *y1, *n1, *hbuf, *y2;
    cudaGetSymbolAddress((void**)&q,    g_q);
    cudaGetSymbolAddress((void**)&k,    g_k);
    cudaGetSymbolAddress((void**)&v,    g_v);
    cudaGetSymbolAddress((void**)&ctx,  g_ctx);
    cudaGetSymbolAddress((void**)&y1,   g_y1);
    cudaGetSymbolAddress((void**)&n1,   g_n1);
    cudaGetSymbolAddress((void**)&hbuf, g_h);
    cudaGetSymbolAddress((void**)&y2,   g_y2);

    cudaFuncSetAttribute(flash_attn, cudaFuncAttributeMaxDynamicSharedMemorySize, FLASH_SMEM);

    dim3 blk(256);
    dim3 gp768(768 / 128, M_TOK / 128);    // (6, 64)
    dim3 gp3072(3072 / 128, M_TOK / 128);  // (24, 64)

    // QKV projections
    gemm_nt<0><<<gp768, blk>>>(x, wq, bq, nullptr, q, M_TOK, D_MODEL, D_MODEL);
    gemm_nt<0><<<gp768, blk>>>(x, wk, bk, nullptr, k, M_TOK, D_MODEL, D_MODEL);
    gemm_nt<0><<<gp768, blk>>>(x, wv, bv, nullptr, v, M_TOK, D_MODEL, D_MODEL);
    // attention
    flash_attn<<<dim3(32, 24), blk, FLASH_SMEM>>>(q, k, v, ctx);
    // output projection + residual(x)
    gemm_nt<2><<<gp768, blk>>>(ctx, wo, bo, x, y1, M_TOK, D_MODEL, D_MODEL);
    layernorm_k<<<M_TOK, blk>>>(y1, g1, be1, n1);
    // FFN
    gemm_nt<1><<<gp3072, blk>>>(n1, w1, b1, nullptr, hbuf, M_TOK, D_FFN, D_MODEL);
    gemm_nt<2><<<gp768, blk>>>(hbuf, w2, b2, n1, y2, M_TOK, D_MODEL, D_FFN);
    layernorm_k<<<M_TOK, blk>>>(y2, g2, be2, out);
}

// round 4
// speedup vs baseline: 1.5293x; 1.0700x over previous
#include <cuda_runtime.h>
#include <math.h>

#define DEVINL __device__ __forceinline__

typedef unsigned long long u64;

// ---------------- packed f32x2 helpers (sm_100+ PTX) ----------------
DEVINL u64 pack2(float lo, float hi) {
    u64 r;
    asm("mov.b64 %0, {%1, %2};" : "=l"(r) : "f"(lo), "f"(hi));
    return r;
}
DEVINL void unpack2(u64 v, float &lo, float &hi) {
    asm("mov.b64 {%0, %1}, %2;" : "=f"(lo), "=f"(hi) : "l"(v));
}
DEVINL void fma2(u64 &d, u64 a, u64 b) {
    asm("fma.rn.f32x2 %0, %1, %2, %0;" : "+l"(d) : "l"(a), "l"(b));
}
DEVINL void mul2(u64 &d, u64 a) {
    asm("mul.rn.f32x2 %0, %0, %1;" : "+l"(d) : "l"(a));
}

DEVINL float gelu_exact(float x) {
    return 0.5f * x * (1.0f + erff(x * 0.7071067811865475f));
}

// ---------------- problem constants ----------------
static const int M_TOK = 8192;
static const int D_MODEL = 768;
static const int D_FFN = 3072;

// ---------------- scratch (device globals; no allocations allowed) ----------------
__device__ float g_q[8192 * 768];
__device__ float g_k[8192 * 768];
__device__ float g_v[8192 * 768];
__device__ float g_ctx[8192 * 768];
__device__ float g_y1[8192 * 768];
__device__ float g_n1[8192 * 768];
__device__ float g_h[8192 * 3072];
__device__ float g_y2[8192 * 768];

// =====================================================================
// NT SGEMM: C[M,N] = A[M,K] @ B[N,K]^T (+ bias, + epilogue)
// EPI: 0 = +bias, 1 = +bias then exact GELU, 2 = +bias +residual
// BM=BN=128, BK=16, 256 threads, 8x8 per thread, f32x2 accumulators.
// DOUBLE-BUFFERED smem (2 stages x 16KB each for A and B): one
// __syncthreads per K-tile; 2 blocks/SM via __launch_bounds__(256,2).
// =====================================================================
template <int EPI>
__global__ void __launch_bounds__(256, 2) gemm_nt(
    const float* __restrict__ A,
    const float* __restrict__ B,
    const float* __restrict__ bias,
    const float* __restrict__ res,
    float* __restrict__ C,
    int M, int N, int K)
{
    __shared__ float As[2][16][128];
    __shared__ float Bs[2][16][128];

    const int tid = threadIdx.x;
    const int bm = blockIdx.y * 128;
    const int bn = blockIdx.x * 128;

    const int lr = tid >> 2;           // 0..63
    const int lc = (tid & 3) << 2;     // 0,4,8,12
    const float* Ag = A + (long)(bm + lr) * K + lc;
    const float* Bg = B + (long)(bn + lr) * K + lc;

    const int ty = tid >> 4;           // 0..15
    const int tx = tid & 15;           // 0..15

    u64 acc[8][4];
#pragma unroll
    for (int i = 0; i < 8; i++)
#pragma unroll
        for (int j = 0; j < 4; j++) acc[i][j] = 0ull;

    float4 pa0, pa1, pb0, pb1;

    // prologue: load tile 0 into stage 0
    pa0 = *(const float4*)(Ag);
    pa1 = *(const float4*)(Ag + (long)64 * K);
    pb0 = *(const float4*)(Bg);
    pb1 = *(const float4*)(Bg + (long)64 * K);
    As[0][lc + 0][lr] = pa0.x; As[0][lc + 1][lr] = pa0.y; As[0][lc + 2][lr] = pa0.z; As[0][lc + 3][lr] = pa0.w;
    As[0][lc + 0][lr + 64] = pa1.x; As[0][lc + 1][lr + 64] = pa1.y; As[0][lc + 2][lr + 64] = pa1.z; As[0][lc + 3][lr + 64] = pa1.w;
    Bs[0][lc + 0][lr] = pb0.x; Bs[0][lc + 1][lr] = pb0.y; Bs[0][lc + 2][lr] = pb0.z; Bs[0][lc + 3][lr] = pb0.w;
    Bs[0][lc + 0][lr + 64] = pb1.x; Bs[0][lc + 1][lr + 64] = pb1.y; Bs[0][lc + 2][lr + 64] = pb1.z; Bs[0][lc + 3][lr + 64] = pb1.w;
    __syncthreads();

    const int nk = K >> 4;
    for (int t = 0; t < nk; ++t) {
        const int cur = t & 1;
        const int nxt = cur ^ 1;
        if (t + 1 < nk) {
            const float* Ap = Ag + (t + 1) * 16;
            const float* Bp = Bg + (t + 1) * 16;
            pa0 = *(const float4*)(Ap);
            pa1 = *(const float4*)(Ap + (long)64 * K);
            pb0 = *(const float4*)(Bp);
            pb1 = *(const float4*)(Bp + (long)64 * K);
        }
#pragma unroll
        for (int kk = 0; kk < 16; kk++) {
            float4 a0 = *(const float4*)(&As[cur][kk][ty * 4]);
            float4 a1 = *(const float4*)(&As[cur][kk][64 + ty * 4]);
            ulonglong2 b0 = *(const ulonglong2*)(&Bs[cur][kk][tx * 4]);
            ulonglong2 b1 = *(const ulonglong2*)(&Bs[cur][kk][64 + tx * 4]);
            float ar[8] = {a0.x, a0.y, a0.z, a0.w, a1.x, a1.y, a1.z, a1.w};
#pragma unroll
            for (int i = 0; i < 8; i++) {
                u64 ap = pack2(ar[i], ar[i]);
                fma2(acc[i][0], ap, b0.x);
                fma2(acc[i][1], ap, b0.y);
                fma2(acc[i][2], ap, b1.x);
                fma2(acc[i][3], ap, b1.y);
            }
        }
        if (t + 1 < nk) {
            As[nxt][lc + 0][lr] = pa0.x; As[nxt][lc + 1][lr] = pa0.y; As[nxt][lc + 2][lr] = pa0.z; As[nxt][lc + 3][lr] = pa0.w;
            As[nxt][lc + 0][lr + 64] = pa1.x; As[nxt][lc + 1][lr + 64] = pa1.y; As[nxt][lc + 2][lr + 64] = pa1.z; As[nxt][lc + 3][lr + 64] = pa1.w;
            Bs[nxt][lc + 0][lr] = pb0.x; Bs[nxt][lc + 1][lr] = pb0.y; Bs[nxt][lc + 2][lr] = pb0.z; Bs[nxt][lc + 3][lr] = pb0.w;
            Bs[nxt][lc + 0][lr + 64] = pb1.x; Bs[nxt][lc + 1][lr + 64] = pb1.y; Bs[nxt][lc + 2][lr + 64] = pb1.z; Bs[nxt][lc + 3][lr + 64] = pb1.w;
            __syncthreads();
        }
    }

    // epilogue
#pragma unroll
    for (int i = 0; i < 8; i++) {
        int lm = (i < 4) ? (ty * 4 + i) : (64 + ty * 4 + (i - 4));
        long gm = bm + lm;
#pragma unroll
        for (int q2 = 0; q2 < 2; q2++) {
            int gn = bn + q2 * 64 + tx * 4;
            float x0, x1, x2, x3;
            unpack2(acc[i][q2 * 2 + 0], x0, x1);
            unpack2(acc[i][q2 * 2 + 1], x2, x3);
            float4 bv = *(const float4*)(bias + gn);
            x0 += bv.x; x1 += bv.y; x2 += bv.z; x3 += bv.w;
            if (EPI == 1) {
                x0 = gelu_exact(x0); x1 = gelu_exact(x1);
                x2 = gelu_exact(x2); x3 = gelu_exact(x3);
            }
            if (EPI == 2) {
                float4 rv = *(const float4*)(res + gm * N + gn);
                x0 += rv.x; x1 += rv.y; x2 += rv.z; x3 += rv.w;
            }
            float4 ov = make_float4(x0, x1, x2, x3);
            *(float4*)(C + gm * N + gn) = ov;
        }
    }
}

// =====================================================================
// fp32 flash attention v3: BM=128 q-rows, BN=64 keys, d_k=64.
// 256 threads (16x16). S fragment 8x4, O fragment 8x4 (f32x2 over d).
// smem = QsT[64][132] + KsT[64][68] + Vs[64][64] + Ps[128][68]
//      = 102400 B  ->  2 blocks/SM (launch_bounds(256,2)).
// Grid: (S/128, B*H) = (32, 24).
// =====================================================================
#define FL_QPAD 132
#define FL_KPAD 68
#define FLASH_SMEM ((64 * FL_QPAD + 64 * FL_KPAD + 64 * 64 + 128 * FL_KPAD) * 4)

__global__ void __launch_bounds__(256, 2) flash_attn(
    const float* __restrict__ Q,
    const float* __restrict__ Kg,
    const float* __restrict__ Vg,
    float* __restrict__ O)
{
    extern __shared__ float sm[];
    float* QsT = sm;                         // [64][132] (k-major, q contiguous)
    float* KsT = QsT + 64 * FL_QPAD;         // [64][68]  (k-major, key contiguous)
    float* Vs  = KsT + 64 * FL_KPAD;         // [64][64]  (key-major, d contiguous)
    float* Ps  = Vs + 64 * 64;               // [128][68] (q-major, key contiguous)

    const int tid = threadIdx.x;
    const int ty = tid >> 4;                 // 0..15
    const int tx = tid & 15;                 // 0..15
    const int bh = blockIdx.y;
    const int b = bh / 12;
    const int h = bh - b * 12;
    const int q0 = blockIdx.x * 128;
    const long rowbase = (long)b * 4096;

    const int r = tid >> 4;                  // staging row lane 0..15
    const int c = (tid & 15) * 4;            // staging col 0,4,..,60

    // ---- stage Q transposed, pre-scaled by 1/sqrt(64) ----
    {
        const float* Qb = Q + (rowbase + q0) * 768 + h * 64;
#pragma unroll
        for (int p = 0; p < 8; p++) {
            int row = p * 16 + r;
            float4 v = *(const float4*)(Qb + (long)row * 768 + c);
            QsT[(c + 0) * FL_QPAD + row] = v.x * 0.125f;
            QsT[(c + 1) * FL_QPAD + row] = v.y * 0.125f;
            QsT[(c + 2) * FL_QPAD + row] = v.z * 0.125f;
            QsT[(c + 3) * FL_QPAD + row] = v.w * 0.125f;
        }
    }

    u64 o[8][2];
    float m_i[8], l_i[8];
#pragma unroll
    for (int i = 0; i < 8; i++) { o[i][0] = 0ull; o[i][1] = 0ull; m_i[i] = -1e30f; l_i[i] = 0.0f; }

    int qr[8];
#pragma unroll
    for (int i = 0; i < 8; i++) qr[i] = (i < 4) ? (ty * 4 + i) : (64 + ty * 4 + (i - 4));

    for (int kt = 0; kt < 64; ++kt) {
        __syncthreads();   // prev PV reads of Vs/Ps done; fences QsT on iter 0
        // ---- stage K (transposed) and V (natural), 64 keys ----
        {
            const float* Kb = Kg + (rowbase + kt * 64) * 768 + h * 64;
            const float* Vb = Vg + (rowbase + kt * 64) * 768 + h * 64;
#pragma unroll
            for (int p = 0; p < 4; p++) {
                int row = p * 16 + r;
                float4 kv = *(const float4*)(Kb + (long)row * 768 + c);
                KsT[(c + 0) * FL_KPAD + row] = kv.x;
                KsT[(c + 1) * FL_KPAD + row] = kv.y;
                KsT[(c + 2) * FL_KPAD + row] = kv.z;
                KsT[(c + 3) * FL_KPAD + row] = kv.w;
                *(float4*)(Vs + row * 64 + c) = *(const float4*)(Vb + (long)row * 768 + c);
            }
        }
        __syncthreads();

        // ---- S = Q K^T: 8 q-rows x 4 keys per thread ----
        u64 s2[8][2];
#pragma unroll
        for (int i = 0; i < 8; i++) { s2[i][0] = 0ull; s2[i][1] = 0ull; }

#pragma unroll 8
        for (int k = 0; k < 64; k++) {
            float4 a0 = *(const float4*)(QsT + k * FL_QPAD + ty * 4);
            float4 a1 = *(const float4*)(QsT + k * FL_QPAD + 64 + ty * 4);
            ulonglong2 b0 = *(const ulonglong2*)(KsT + k * FL_KPAD + tx * 4);
            float ar[8] = {a0.x, a0.y, a0.z, a0.w, a1.x, a1.y, a1.z, a1.w};
#pragma unroll
            for (int i = 0; i < 8; i++) {
                u64 ap = pack2(ar[i], ar[i]);
                fma2(s2[i][0], ap, b0.x);
                fma2(s2[i][1], ap, b0.y);
            }
        }

        // ---- online softmax; write P (natural layout) ----
#pragma unroll
        for (int i = 0; i < 8; i++) {
            float s0, s1, s2f, s3;
            unpack2(s2[i][0], s0, s1);
            unpack2(s2[i][1], s2f, s3);
            float mx = fmaxf(fmaxf(s0, s1), fmaxf(s2f, s3));
#pragma unroll
            for (int d = 8; d; d >>= 1) mx = fmaxf(mx, __shfl_xor_sync(0xffffffffu, mx, d));
            float mn = fmaxf(m_i[i], mx);
            float alpha = __expf(m_i[i] - mn);
            m_i[i] = mn;
            float p0 = __expf(s0 - mn), p1 = __expf(s1 - mn);
            float p2 = __expf(s2f - mn), p3 = __expf(s3 - mn);
            float rs = (p0 + p1) + (p2 + p3);
#pragma unroll
            for (int d = 8; d; d >>= 1) rs += __shfl_xor_sync(0xffffffffu, rs, d);
            l_i[i] = l_i[i] * alpha + rs;
            u64 ap = pack2(alpha, alpha);
            mul2(o[i][0], ap);
            mul2(o[i][1], ap);
            *(float4*)(Ps + qr[i] * FL_KPAD + tx * 4) = make_float4(p0, p1, p2, p3);
        }
        __syncthreads();

        // ---- O += P V ----
#pragma unroll 2
        for (int kk4 = 0; kk4 < 16; kk4++) {
            float4 pr[8];
#pragma unroll
            for (int i = 0; i < 8; i++)
                pr[i] = *(const float4*)(Ps + qr[i] * FL_KPAD + kk4 * 4);
            ulonglong2 vv[4];
#pragma unroll
            for (int u = 0; u < 4; u++)
                vv[u] = *(const ulonglong2*)(Vs + (kk4 * 4 + u) * 64 + tx * 4);
#pragma unroll
            for (int u = 0; u < 4; u++) {
#pragma unroll
                for (int i = 0; i < 8; i++) {
                    float pv = (u == 0) ? pr[i].x : (u == 1) ? pr[i].y : (u == 2) ? pr[i].z : pr[i].w;
                    u64 pp = pack2(pv, pv);
                    fma2(o[i][0], pp, vv[u].x);
                    fma2(o[i][1], pp, vv[u].y);
                }
            }
        }
    }

    // ---- normalize and write out ----
    float* Ob = O + (rowbase + q0) * 768 + h * 64;
#pragma unroll
    for (int i = 0; i < 8; i++) {
        float inv = 1.0f / l_i[i];
        float c0, c1, c2, c3;
        unpack2(o[i][0], c0, c1);
        unpack2(o[i][1], c2, c3);
        float4 ov = make_float4(c0 * inv, c1 * inv, c2 * inv, c3 * inv);
        *(float4*)(Ob + (long)qr[i] * 768 + tx * 4) = ov;
    }
}

// =====================================================================
// LayerNorm over last dim (768). One block (256 thr) per row.
// =====================================================================
__global__ void __launch_bounds__(256) layernorm_k(
    const float* __restrict__ X,
    const float* __restrict__ g,
    const float* __restrict__ bta,
    float* __restrict__ Y)
{
    const long row = blockIdx.x;
    const float* x = X + row * 768;
    const int tid = threadIdx.x;
    float v0 = x[tid], v1 = x[tid + 256], v2 = x[tid + 512];
    float s = v0 + v1 + v2;
    float ss = v0 * v0 + v1 * v1 + v2 * v2;
#pragma unroll
    for (int d = 16; d; d >>= 1) {
        s += __shfl_xor_sync(0xffffffffu, s, d);
        ss += __shfl_xor_sync(0xffffffffu, ss, d);
    }
    __shared__ float r0[8], r1[8];
    if ((tid & 31) == 0) { r0[tid >> 5] = s; r1[tid >> 5] = ss; }
    __syncthreads();
    float tot = 0.0f, tot2 = 0.0f;
#pragma unroll
    for (int w = 0; w < 8; w++) { tot += r0[w]; tot2 += r1[w]; }
    const float invD = 1.0f / 768.0f;
    float mu = tot * invD;
    float var = tot2 * invD - mu * mu;
    float rstd = rsqrtf(var + 1e-5f);
    float* y = Y + row * 768;
    y[tid]       = (v0 - mu) * rstd * g[tid]       + bta[tid];
    y[tid + 256] = (v1 - mu) * rstd * g[tid + 256] + bta[tid + 256];
    y[tid + 512] = (v2 - mu) * rstd * g[tid + 512] + bta[tid + 512];
}

// =====================================================================
// host launcher (graph-capturable: kernel launches only)
// =====================================================================
extern "C" void kernel_launch(void* const* d_in, const int* in_sizes, int n_in,
                              void* d_out, int out_size)
{
    (void)in_sizes; (void)n_in; (void)out_size;
    const float* x   = (const float*)d_in[0];
    const float* wq  = (const float*)d_in[1];
    const float* bq  = (const float*)d_in[2];
    const float* wk  = (const float*)d_in[3];
    const float* bk  = (const float*)d_in[4];
    const float* wv  = (const float*)d_in[5];
    const float* bv  = (const float*)d_in[6];
    const float* wo  = (const float*)d_in[7];
    const float* bo  = (const float*)d_in[8];
    const float* w1  = (const float*)d_in[9];
    const float* b1  = (const float*)d_in[10];
    const float* w2  = (const float*)d_in[11];
    const float* b2  = (const float*)d_in[12];
    const float* g1  = (const float*)d_in[13];
    const float* be1 = (const float*)d_in[14];
    const float* g2  = (const float*)d_in[15];
    const float* be2 = (const float*)d_in[16];
    float* out = (float*)d_out;

    float *q, *k, *v, *ctx, *y1, *n1, *hbuf, *y2;
    cudaGetSymbolAddress((void**)&q,    g_q);
    cudaGetSymbolAddress((void**)&k,    g_k);
    cudaGetSymbolAddress((void**)&v,    g_v);
    cudaGetSymbolAddress((void**)&ctx,  g_ctx);
    cudaGetSymbolAddress((void**)&y1,   g_y1);
    cudaGetSymbolAddress((void**)&n1,   g_n1);
    cudaGetSymbolAddress((void**)&hbuf, g_h);
    cudaGetSymbolAddress((void**)&y2,   g_y2);

    cudaFuncSetAttribute(flash_attn, cudaFuncAttributeMaxDynamicSharedMemorySize, FLASH_SMEM);

    dim3 blk(256);
    dim3 gp768(768 / 128, M_TOK / 128);    // (6, 64)
    dim3 gp3072(3072 / 128, M_TOK / 128);  // (24, 64)

    // QKV projections
    gemm_nt<0><<<gp768, blk>>>(x, wq, bq, nullptr, q, M_TOK, D_MODEL, D_MODEL);
    gemm_nt<0><<<gp768, blk>>>(x, wk, bk, nullptr, k, M_TOK, D_MODEL, D_MODEL);
    gemm_nt<0><<<gp768, blk>>>(x, wv, bv, nullptr, v, M_TOK, D_MODEL, D_MODEL);
    // attention
    flash_attn<<<dim3(32, 24), blk, FLASH_SMEM>>>(q, k, v, ctx);
    // output projection + residual(x)
    gemm_nt<2><<<gp768, blk>>>(ctx, wo, bo, x, y1, M_TOK, D_MODEL, D_MODEL);
    layernorm_k<<<M_TOK, blk>>>(y1, g1, be1, n1);
    // FFN
    gemm_nt<1><<<gp3072, blk>>>(n1, w1, b1, nullptr, hbuf, M_TOK, D_FFN, D_MODEL);
    gemm_nt<2><<<gp768, blk>>>(hbuf, w2, b2, n1, y2, M_TOK, D_MODEL, D_FFN);
    layernorm_k<<<M_TOK, blk>>>(y2, g2, be2, out);
}